// round 1
// baseline (speedup 1.0000x reference)
#include <cuda_runtime.h>
#include <cstdint>

// ---------------------------------------------------------------------------
// Problem constants
// ---------------------------------------------------------------------------
#define DIM_  1024
#define B_    8
#define TI_   2048
#define TJ_   2048
#define EPS_  1e-5f
#define NROWS_T (B_*TI_)   // 16384
#define NROWS_S (B_*TJ_)   // 16384

// ---------------------------------------------------------------------------
// Scratch (device globals — sanctioned workaround for no-alloc rule)
// ---------------------------------------------------------------------------
__device__ float g_ln_t[(size_t)NROWS_T * DIM_];
__device__ float g_ln_k[(size_t)NROWS_S * DIM_];
__device__ float g_ln_v[(size_t)NROWS_S * DIM_];
__device__ float g_q  [(size_t)NROWS_T * DIM_];
__device__ float g_k  [(size_t)NROWS_S * DIM_];
__device__ float g_v  [(size_t)NROWS_S * DIM_];
__device__ float g_S  [(size_t)B_ * TI_ * TJ_];

// ---------------------------------------------------------------------------
// LayerNorm: one block (256 thr) per row of 1024
// ---------------------------------------------------------------------------
__global__ void ln_kernel(const float* __restrict__ x,
                          const float* __restrict__ gamma,
                          const float* __restrict__ beta,
                          float* __restrict__ out) {
    const size_t row = blockIdx.x;
    const float4* xr = reinterpret_cast<const float4*>(x + row * DIM_);
    float4* outr = reinterpret_cast<float4*>(out + row * DIM_);

    float4 xv = xr[threadIdx.x];
    float s  = xv.x + xv.y + xv.z + xv.w;
    float s2 = xv.x*xv.x + xv.y*xv.y + xv.z*xv.z + xv.w*xv.w;

    #pragma unroll
    for (int o = 16; o; o >>= 1) {
        s  += __shfl_xor_sync(0xffffffffu, s,  o);
        s2 += __shfl_xor_sync(0xffffffffu, s2, o);
    }
    __shared__ float sh_s[8], sh_s2[8];
    const int w = threadIdx.x >> 5, l = threadIdx.x & 31;
    if (l == 0) { sh_s[w] = s; sh_s2[w] = s2; }
    __syncthreads();
    float ts = 0.f, ts2 = 0.f;
    #pragma unroll
    for (int i = 0; i < 8; i++) { ts += sh_s[i]; ts2 += sh_s2[i]; }

    const float mean = ts * (1.0f / DIM_);
    const float var  = ts2 * (1.0f / DIM_) - mean * mean;
    const float inv  = rsqrtf(var + EPS_);

    const float4 gv = reinterpret_cast<const float4*>(gamma)[threadIdx.x];
    const float4 bv = reinterpret_cast<const float4*>(beta)[threadIdx.x];
    float4 o4;
    o4.x = (xv.x - mean) * inv * gv.x + bv.x;
    o4.y = (xv.y - mean) * inv * gv.y + bv.y;
    o4.z = (xv.z - mean) * inv * gv.z + bv.z;
    o4.w = (xv.w - mean) * inv * gv.w + bv.w;
    outr[threadIdx.x] = o4;
}

// ---------------------------------------------------------------------------
// Row softmax over TJ_ = 2048: one block (256 thr) per row, in place
// ---------------------------------------------------------------------------
__global__ void softmax_kernel(float* __restrict__ S) {
    const size_t row = blockIdx.x;
    float4* r4 = reinterpret_cast<float4*>(S + row * (size_t)TJ_);

    float4 v[2];
    float mx = -3.4e38f;
    #pragma unroll
    for (int i = 0; i < 2; i++) {
        v[i] = r4[threadIdx.x + i * 256];
        mx = fmaxf(mx, fmaxf(fmaxf(v[i].x, v[i].y), fmaxf(v[i].z, v[i].w)));
    }
    #pragma unroll
    for (int o = 16; o; o >>= 1) mx = fmaxf(mx, __shfl_xor_sync(0xffffffffu, mx, o));
    __shared__ float sh_m[8], sh_sum[8];
    const int w = threadIdx.x >> 5, l = threadIdx.x & 31;
    if (l == 0) sh_m[w] = mx;
    __syncthreads();
    mx = sh_m[0];
    #pragma unroll
    for (int i = 1; i < 8; i++) mx = fmaxf(mx, sh_m[i]);

    float sum = 0.f;
    #pragma unroll
    for (int i = 0; i < 2; i++) {
        v[i].x = __expf(v[i].x - mx);
        v[i].y = __expf(v[i].y - mx);
        v[i].z = __expf(v[i].z - mx);
        v[i].w = __expf(v[i].w - mx);
        sum += v[i].x + v[i].y + v[i].z + v[i].w;
    }
    #pragma unroll
    for (int o = 16; o; o >>= 1) sum += __shfl_xor_sync(0xffffffffu, sum, o);
    if (l == 0) sh_sum[w] = sum;
    __syncthreads();
    sum = 0.f;
    #pragma unroll
    for (int i = 0; i < 8; i++) sum += sh_sum[i];
    const float inv = 1.0f / sum;
    #pragma unroll
    for (int i = 0; i < 2; i++) {
        v[i].x *= inv; v[i].y *= inv; v[i].z *= inv; v[i].w *= inv;
        r4[threadIdx.x + i * 256] = v[i];
    }
}

// ---------------------------------------------------------------------------
// tf32 mma.sync GEMM
//   TRANS_B = true : C[m,n] = scale * sum_k A[m,k] * B[n,k]  (+ bias[n])
//   TRANS_B = false: C[m,n] = scale * sum_k A[m,k] * B[k,n]  (+ bias[n])
// All dims assumed multiples of tile sizes (true for this problem).
// ---------------------------------------------------------------------------
constexpr int BM = 128, BN = 128, BK = 32;

__device__ __forceinline__ uint32_t f2tf32(float f) {
    uint32_t u;
    asm("cvt.rna.tf32.f32 %0, %1;" : "=r"(u) : "f"(f));
    return u;
}

template <bool TRANS_B, bool HAS_BIAS>
__global__ __launch_bounds__(256, 2)
void gemm_tf32_kernel(const float* __restrict__ A, const float* __restrict__ Bm,
                      const float* __restrict__ bias, float* __restrict__ C,
                      int M, int N, int K, float scale,
                      long long bsA, long long bsB, long long bsC) {
    const int z = blockIdx.z;
    A  += (size_t)z * bsA;
    Bm += (size_t)z * bsB;
    C  += (size_t)z * bsC;

    const int bm = blockIdx.y * BM;
    const int bn = blockIdx.x * BN;

    constexpr int LDA = BK + 4;                     // 36 words: conflict-free frag reads
    constexpr int LDB = TRANS_B ? (BK + 4) : (BN + 8);  // 36 or 136 (8k+j banks)
    __shared__ uint32_t As[BM * LDA];
    __shared__ uint32_t Bs[TRANS_B ? (BN * LDB) : (BK * LDB)];

    const int tid  = threadIdx.x;
    const int warp = tid >> 5, lane = tid & 31;
    const int wm = (warp >> 1) * 32;   // warp row base within tile (4 warps on M)
    const int wn = (warp & 1) * 64;    // warp col base within tile (2 warps on N)

    float acc[2][8][4];
    #pragma unroll
    for (int i = 0; i < 2; i++)
        #pragma unroll
        for (int j = 0; j < 8; j++)
            #pragma unroll
            for (int c = 0; c < 4; c++) acc[i][j][c] = 0.f;

    // loader mappings
    const int ar = tid >> 3;          // 0..31   (row within 32-row stripe)
    const int ac = (tid & 7) * 4;     // 0,4,...,28
    const int br = tid >> 5;          // 0..7    (k row for NN)
    const int bc = (tid & 31) * 4;    // 0..124

    for (int k0 = 0; k0 < K; k0 += BK) {
        __syncthreads();   // protect smem from previous iteration's readers
        #pragma unroll
        for (int i = 0; i < 4; i++) {
            const int row = ar + i * 32;
            const float4 av = *reinterpret_cast<const float4*>(
                A + (size_t)(bm + row) * K + k0 + ac);
            uint32_t* d = &As[row * LDA + ac];
            d[0] = f2tf32(av.x); d[1] = f2tf32(av.y);
            d[2] = f2tf32(av.z); d[3] = f2tf32(av.w);
        }
        if (TRANS_B) {
            #pragma unroll
            for (int i = 0; i < 4; i++) {
                const int row = ar + i * 32;
                const float4 bv = *reinterpret_cast<const float4*>(
                    Bm + (size_t)(bn + row) * K + k0 + ac);
                uint32_t* d = &Bs[row * LDB + ac];
                d[0] = f2tf32(bv.x); d[1] = f2tf32(bv.y);
                d[2] = f2tf32(bv.z); d[3] = f2tf32(bv.w);
            }
        } else {
            #pragma unroll
            for (int i = 0; i < 4; i++) {
                const int krow = br + i * 8;
                const float4 bv = *reinterpret_cast<const float4*>(
                    Bm + (size_t)(k0 + krow) * N + bn + bc);
                uint32_t* d = &Bs[krow * LDB + bc];
                d[0] = f2tf32(bv.x); d[1] = f2tf32(bv.y);
                d[2] = f2tf32(bv.z); d[3] = f2tf32(bv.w);
            }
        }
        __syncthreads();

        #pragma unroll
        for (int kk = 0; kk < BK; kk += 8) {
            uint32_t af[2][4];
            #pragma unroll
            for (int mf = 0; mf < 2; mf++) {
                const int r0 = wm + mf * 16 + (lane >> 2);
                const int c0 = kk + (lane & 3);
                af[mf][0] = As[r0 * LDA + c0];
                af[mf][1] = As[(r0 + 8) * LDA + c0];
                af[mf][2] = As[r0 * LDA + c0 + 4];
                af[mf][3] = As[(r0 + 8) * LDA + c0 + 4];
            }
            uint32_t bf[8][2];
            #pragma unroll
            for (int nf = 0; nf < 8; nf++) {
                const int n0 = wn + nf * 8 + (lane >> 2);
                const int kc = kk + (lane & 3);
                if (TRANS_B) {
                    bf[nf][0] = Bs[n0 * LDB + kc];
                    bf[nf][1] = Bs[n0 * LDB + kc + 4];
                } else {
                    bf[nf][0] = Bs[kc * LDB + n0];
                    bf[nf][1] = Bs[(kc + 4) * LDB + n0];
                }
            }
            #pragma unroll
            for (int mf = 0; mf < 2; mf++)
                #pragma unroll
                for (int nf = 0; nf < 8; nf++) {
                    asm volatile(
                        "mma.sync.aligned.m16n8k8.row.col.f32.tf32.tf32.f32 "
                        "{%0,%1,%2,%3}, {%4,%5,%6,%7}, {%8,%9}, {%0,%1,%2,%3};"
                        : "+f"(acc[mf][nf][0]), "+f"(acc[mf][nf][1]),
                          "+f"(acc[mf][nf][2]), "+f"(acc[mf][nf][3])
                        : "r"(af[mf][0]), "r"(af[mf][1]),
                          "r"(af[mf][2]), "r"(af[mf][3]),
                          "r"(bf[nf][0]), "r"(bf[nf][1]));
                }
        }
    }

    // epilogue
    #pragma unroll
    for (int mf = 0; mf < 2; mf++) {
        const int r0 = bm + wm + mf * 16 + (lane >> 2);
        #pragma unroll
        for (int nf = 0; nf < 8; nf++) {
            const int c0 = bn + wn + nf * 8 + 2 * (lane & 3);
            const float bb0 = HAS_BIAS ? bias[c0]     : 0.f;
            const float bb1 = HAS_BIAS ? bias[c0 + 1] : 0.f;
            C[(size_t)r0 * N + c0]           = acc[mf][nf][0] * scale + bb0;
            C[(size_t)r0 * N + c0 + 1]       = acc[mf][nf][1] * scale + bb1;
            C[(size_t)(r0 + 8) * N + c0]     = acc[mf][nf][2] * scale + bb0;
            C[(size_t)(r0 + 8) * N + c0 + 1] = acc[mf][nf][3] * scale + bb1;
        }
    }
}

// ---------------------------------------------------------------------------
// Launch
// ---------------------------------------------------------------------------
extern "C" void kernel_launch(void* const* d_in, const int* in_sizes, int n_in,
                              void* d_out, int out_size) {
    (void)in_sizes; (void)n_in; (void)out_size;
    const float* target   = (const float*)d_in[0];
    const float* source_k = (const float*)d_in[1];
    const float* source_v = (const float*)d_in[2];
    const float* Wq = (const float*)d_in[3];
    const float* bq = (const float*)d_in[4];
    const float* Wk = (const float*)d_in[5];
    const float* bk = (const float*)d_in[6];
    const float* Wv = (const float*)d_in[7];
    const float* bv = (const float*)d_in[8];
    const float* gt = (const float*)d_in[9];
    const float* bt = (const float*)d_in[10];
    const float* gk = (const float*)d_in[11];
    const float* bk_ln = (const float*)d_in[12];
    const float* gv = (const float*)d_in[13];
    const float* bv_ln = (const float*)d_in[14];
    float* out = (float*)d_out;

    float *ln_t, *ln_k, *ln_v, *q, *k, *v, *S;
    cudaGetSymbolAddress((void**)&ln_t, g_ln_t);
    cudaGetSymbolAddress((void**)&ln_k, g_ln_k);
    cudaGetSymbolAddress((void**)&ln_v, g_ln_v);
    cudaGetSymbolAddress((void**)&q,    g_q);
    cudaGetSymbolAddress((void**)&k,    g_k);
    cudaGetSymbolAddress((void**)&v,    g_v);
    cudaGetSymbolAddress((void**)&S,    g_S);

    // LayerNorms
    ln_kernel<<<NROWS_T, 256>>>(target,   gt, bt,    ln_t);
    ln_kernel<<<NROWS_S, 256>>>(source_k, gk, bk_ln, ln_k);
    ln_kernel<<<NROWS_S, 256>>>(source_v, gv, bv_ln, ln_v);

    // Projections: X @ W^T + b  (W is [out,in] row-major -> TRANS_B)
    dim3 gProj(DIM_ / BN, NROWS_T / BM, 1);
    gemm_tf32_kernel<true,  true><<<gProj, 256>>>(ln_t, Wq, bq, q,
        NROWS_T, DIM_, DIM_, 1.0f, 0, 0, 0);
    gemm_tf32_kernel<true,  true><<<gProj, 256>>>(ln_k, Wk, bk, k,
        NROWS_S, DIM_, DIM_, 1.0f, 0, 0, 0);
    gemm_tf32_kernel<true,  true><<<gProj, 256>>>(ln_v, Wv, bv, v,
        NROWS_S, DIM_, DIM_, 1.0f, 0, 0, 0);

    // S = (Q K^T) * DIM^-0.5, batched over B_
    dim3 gS(TJ_ / BN, TI_ / BM, B_);
    gemm_tf32_kernel<true, false><<<gS, 256>>>(q, k, nullptr, S,
        TI_, TJ_, DIM_, 0.03125f,
        (long long)TI_ * DIM_, (long long)TJ_ * DIM_, (long long)TI_ * TJ_);

    // softmax rows of S
    softmax_kernel<<<B_ * TI_, 256>>>(S);

    // O = P @ V, batched (V row-major [TJ, DIM] -> NN)
    dim3 gO(DIM_ / BN, TI_ / BM, B_);
    gemm_tf32_kernel<false, false><<<gO, 256>>>(S, v, nullptr, out,
        TI_, DIM_, TJ_, 1.0f,
        (long long)TI_ * TJ_, (long long)TJ_ * DIM_, (long long)TI_ * DIM_);
}

// round 4
// speedup vs baseline: 1.9457x; 1.9457x over previous
#include <cuda_runtime.h>
#include <cstdint>

// ---------------------------------------------------------------------------
// Problem constants
// ---------------------------------------------------------------------------
#define DIM_  1024
#define B_    8
#define TI_   2048
#define TJ_   2048
#define EPS_  1e-5f
#define NROWS_T (B_*TI_)   // 16384
#define NROWS_S (B_*TJ_)   // 16384

// ---------------------------------------------------------------------------
// Scratch (device globals — sanctioned workaround for no-alloc rule)
// ---------------------------------------------------------------------------
__device__ float g_ln_t[(size_t)NROWS_T * DIM_];
__device__ float g_ln_k[(size_t)NROWS_S * DIM_];
__device__ float g_ln_v[(size_t)NROWS_S * DIM_];
__device__ float g_q  [(size_t)NROWS_T * DIM_];
__device__ float g_k  [(size_t)NROWS_S * DIM_];
__device__ float g_v  [(size_t)NROWS_S * DIM_];
__device__ float g_vt [(size_t)NROWS_S * DIM_];   // V transposed per batch: [B][DIM][TJ]
__device__ float g_S  [(size_t)B_ * TI_ * TJ_];
__device__ float g_Wq [(size_t)DIM_ * DIM_];      // RNA-rounded weight copies
__device__ float g_Wk [(size_t)DIM_ * DIM_];
__device__ float g_Wv [(size_t)DIM_ * DIM_];

// ---------------------------------------------------------------------------
// PTX helpers (legacy sm_80-class only — ptxas target here is sm_103 non-'a',
// which rejects all tcgen05/TMEM instructions)
// ---------------------------------------------------------------------------
__device__ __forceinline__ uint32_t smem_u32(const void* p) {
    uint32_t a;
    asm("{ .reg .u64 t; cvta.to.shared.u64 t, %1; cvt.u32.u64 %0, t; }"
        : "=r"(a) : "l"(p));
    return a;
}

// round-to-nearest fp32 -> tf32 (value kept in fp32 storage, low bits zero)
__device__ __forceinline__ float rna_tf32(float f) {
    uint32_t u;
    asm("cvt.rna.tf32.f32 %0, %1;" : "=r"(u) : "f"(f));
    return __uint_as_float(u);
}

#define CP_ASYNC16(dst_u32, src_ptr) \
    asm volatile("cp.async.cg.shared.global [%0], [%1], 16;\n" \
                 :: "r"(dst_u32), "l"(src_ptr))
#define CP_COMMIT() asm volatile("cp.async.commit_group;\n" ::: "memory")
#define CP_WAIT(n)  asm volatile("cp.async.wait_group %0;\n" :: "n"(n) : "memory")

#define LDSM4(r0, r1, r2, r3, addr) \
    asm volatile("ldmatrix.sync.aligned.m8n8.x4.shared.b16 {%0,%1,%2,%3}, [%4];" \
                 : "=r"(r0), "=r"(r1), "=r"(r2), "=r"(r3) : "r"(addr))

#define MMA_TF32(d0, d1, d2, d3, a0, a1, a2, a3, b0, b1) \
    asm volatile( \
        "mma.sync.aligned.m16n8k8.row.col.f32.tf32.tf32.f32 " \
        "{%0,%1,%2,%3}, {%4,%5,%6,%7}, {%8,%9}, {%0,%1,%2,%3};" \
        : "+f"(d0), "+f"(d1), "+f"(d2), "+f"(d3) \
        : "r"(a0), "r"(a1), "r"(a2), "r"(a3), "r"(b0), "r"(b1))

// ---------------------------------------------------------------------------
// tf32 mma.sync GEMM with cp.async pipeline + ldmatrix fragment loads
//   C[m,n] = scale * sum_k A[m,k]*B[n,k]  (+ bias[n])  [optionally RNA-rounded]
//   A: [M,K] row-major, B: [N,K] row-major. M % 128 == 0, N % 256 == 0, K % 32 == 0.
// CTA tile 128x256, 8 warps of 64x64, BK=32, 4 stages.
// Inputs must already be RNA-rounded to tf32 precision (producers do this).
// ---------------------------------------------------------------------------
constexpr int TBM = 128, TBN = 256, TBK = 32, STAGES = 4;
constexpr int A_BYTES = TBM * TBK * 4;               // 16 KB
constexpr int B_BYTES = TBN * TBK * 4;               // 32 KB
constexpr int STAGE_BYTES = A_BYTES + B_BYTES;       // 48 KB
constexpr int SMEM_TOTAL_GEMM = 1024 + STAGES * STAGE_BYTES;  // ~193 KB

template <bool HAS_BIAS, bool ROUND_OUT>
__global__ __launch_bounds__(256, 1)
void gemm_tc_kernel(const float* __restrict__ A, const float* __restrict__ Bm,
                    const float* __restrict__ bias, float* __restrict__ C,
                    int M, int N, int K, float scale,
                    long long bsA, long long bsB, long long bsC) {
    extern __shared__ char smem[];
    const uint32_t tiles = (smem_u32(smem) + 1023u) & ~1023u;

    const int z = blockIdx.z;
    A  += (size_t)z * bsA;
    Bm += (size_t)z * bsB;
    C  += (size_t)z * bsC;
    const int bm = blockIdx.y * TBM;
    const int bn = blockIdx.x * TBN;

    const int tid  = threadIdx.x;
    const int lane = tid & 31;
    const int w    = tid >> 5;
    const int wm   = (w & 1) * 64;     // warp M base in tile
    const int wn   = (w >> 1) * 64;    // warp N base in tile

    // --- per-lane ldmatrix base offsets (within a stage) ---
    const int rrA = (lane & 7) + (((lane >> 3) & 1) << 3);
    const int csA = (lane >> 4) & 1;
    const int rrB = (lane & 7) + (((lane >> 4) & 1) << 3);
    const int csB = (lane >> 3) & 1;

    uint32_t Aoff[4], Boff[4];
    #pragma unroll
    for (int mf = 0; mf < 4; mf++) {
        const int row = wm + mf * 16 + rrA;
        Aoff[mf] = (uint32_t)(row * 128) + (uint32_t)((((row & 7) ^ csA) << 4));
    }
    #pragma unroll
    for (int nfp = 0; nfp < 4; nfp++) {
        const int row = wn + nfp * 16 + rrB;
        Boff[nfp] = (uint32_t)(row * 128) + (uint32_t)((((row & 7) ^ csB) << 4));
    }

    float acc[4][8][4];
    #pragma unroll
    for (int mf = 0; mf < 4; mf++)
        #pragma unroll
        for (int nf = 0; nf < 8; nf++)
            #pragma unroll
            for (int c = 0; c < 4; c++) acc[mf][nf][c] = 0.f;

    const int nst = K / TBK;

    // --- stage loader: swizzled 16B cp.async (A: 4/thread, B: 8/thread) ---
    auto load_stage = [&](int i) {
        const int s = i & (STAGES - 1);
        const uint32_t ab = tiles + s * STAGE_BYTES;
        const uint32_t bb = ab + A_BYTES;
        const int k0 = i * TBK;
        #pragma unroll
        for (int j = 0; j < 4; j++) {
            const int c   = tid + 256 * j;
            const int row = c >> 3;
            const int c4  = c & 7;
            const uint32_t off = (uint32_t)(row * 128) +
                                 (uint32_t)(((c4 ^ (row & 7)) << 4));
            CP_ASYNC16(ab + off, A + (size_t)(bm + row) * K + k0 + c4 * 4);
        }
        #pragma unroll
        for (int j = 0; j < 8; j++) {
            const int c   = tid + 256 * j;
            const int row = c >> 3;
            const int c4  = c & 7;
            const uint32_t off = (uint32_t)(row * 128) +
                                 (uint32_t)(((c4 ^ (row & 7)) << 4));
            CP_ASYNC16(bb + off, Bm + (size_t)(bn + row) * K + k0 + c4 * 4);
        }
        CP_COMMIT();
    };

    load_stage(0); load_stage(1); load_stage(2);

    for (int i = 0; i < nst; i++) {
        if (i + STAGES - 2 >= nst) { CP_WAIT(0); } else { CP_WAIT(STAGES - 2); }
        __syncthreads();
        if (i + STAGES - 1 < nst) load_stage(i + STAGES - 1);

        const int s = i & (STAGES - 1);
        const uint32_t ab = tiles + s * STAGE_BYTES;
        const uint32_t bb = ab + A_BYTES;

        #pragma unroll
        for (int ks = 0; ks < 4; ks++) {
            const uint32_t cx = (uint32_t)(ks << 5);   // (2*ks) << 4
            uint32_t af[4][4];
            #pragma unroll
            for (int mf = 0; mf < 4; mf++)
                LDSM4(af[mf][0], af[mf][1], af[mf][2], af[mf][3],
                      (ab + Aoff[mf]) ^ cx);
            uint32_t bf[8][2];
            #pragma unroll
            for (int nfp = 0; nfp < 4; nfp++) {
                uint32_t r0, r1, r2, r3;
                LDSM4(r0, r1, r2, r3, (bb + Boff[nfp]) ^ cx);
                bf[2 * nfp][0] = r0;  bf[2 * nfp][1] = r1;
                bf[2 * nfp + 1][0] = r2;  bf[2 * nfp + 1][1] = r3;
            }
            #pragma unroll
            for (int mf = 0; mf < 4; mf++)
                #pragma unroll
                for (int nf = 0; nf < 8; nf++)
                    MMA_TF32(acc[mf][nf][0], acc[mf][nf][1],
                             acc[mf][nf][2], acc[mf][nf][3],
                             af[mf][0], af[mf][1], af[mf][2], af[mf][3],
                             bf[nf][0], bf[nf][1]);
        }
    }

    // --- epilogue ---
    #pragma unroll
    for (int mf = 0; mf < 4; mf++) {
        const int r0 = bm + wm + mf * 16 + (lane >> 2);
        #pragma unroll
        for (int nf = 0; nf < 8; nf++) {
            const int c0 = bn + wn + nf * 8 + 2 * (lane & 3);
            float2 b2 = make_float2(0.f, 0.f);
            if (HAS_BIAS) b2 = *reinterpret_cast<const float2*>(bias + c0);
            float2 o0, o1;
            o0.x = acc[mf][nf][0] * scale + b2.x;
            o0.y = acc[mf][nf][1] * scale + b2.y;
            o1.x = acc[mf][nf][2] * scale + b2.x;
            o1.y = acc[mf][nf][3] * scale + b2.y;
            if (ROUND_OUT) {
                o0.x = rna_tf32(o0.x); o0.y = rna_tf32(o0.y);
                o1.x = rna_tf32(o1.x); o1.y = rna_tf32(o1.y);
            }
            *reinterpret_cast<float2*>(C + (size_t)r0 * N + c0)       = o0;
            *reinterpret_cast<float2*>(C + (size_t)(r0 + 8) * N + c0) = o1;
        }
    }
}

// ---------------------------------------------------------------------------
// RNA-round an array to tf32 precision (for weight matrices)
// ---------------------------------------------------------------------------
__global__ void round_tf32_kernel(const float* __restrict__ in,
                                  float* __restrict__ out, int n4) {
    const int i = blockIdx.x * blockDim.x + threadIdx.x;
    if (i < n4) {
        float4 v = reinterpret_cast<const float4*>(in)[i];
        v.x = rna_tf32(v.x); v.y = rna_tf32(v.y);
        v.z = rna_tf32(v.z); v.w = rna_tf32(v.w);
        reinterpret_cast<float4*>(out)[i] = v;
    }
}

// ---------------------------------------------------------------------------
// LayerNorm: one block (256 thr) per row of 1024; output RNA-rounded to tf32
// ---------------------------------------------------------------------------
__global__ void ln_kernel(const float* __restrict__ x,
                          const float* __restrict__ gamma,
                          const float* __restrict__ beta,
                          float* __restrict__ out) {
    const size_t row = blockIdx.x;
    const float4* xr = reinterpret_cast<const float4*>(x + row * DIM_);
    float4* outr = reinterpret_cast<float4*>(out + row * DIM_);

    float4 xv = xr[threadIdx.x];
    float s  = xv.x + xv.y + xv.z + xv.w;
    float s2 = xv.x*xv.x + xv.y*xv.y + xv.z*xv.z + xv.w*xv.w;

    #pragma unroll
    for (int o = 16; o; o >>= 1) {
        s  += __shfl_xor_sync(0xffffffffu, s,  o);
        s2 += __shfl_xor_sync(0xffffffffu, s2, o);
    }
    __shared__ float sh_s[8], sh_s2[8];
    const int w = threadIdx.x >> 5, l = threadIdx.x & 31;
    if (l == 0) { sh_s[w] = s; sh_s2[w] = s2; }
    __syncthreads();
    float ts = 0.f, ts2 = 0.f;
    #pragma unroll
    for (int i = 0; i < 8; i++) { ts += sh_s[i]; ts2 += sh_s2[i]; }

    const float mean = ts * (1.0f / DIM_);
    const float var  = ts2 * (1.0f / DIM_) - mean * mean;
    const float inv  = rsqrtf(var + EPS_);

    const float4 gv = reinterpret_cast<const float4*>(gamma)[threadIdx.x];
    const float4 bv = reinterpret_cast<const float4*>(beta)[threadIdx.x];
    float4 o4;
    o4.x = rna_tf32((xv.x - mean) * inv * gv.x + bv.x);
    o4.y = rna_tf32((xv.y - mean) * inv * gv.y + bv.y);
    o4.z = rna_tf32((xv.z - mean) * inv * gv.z + bv.z);
    o4.w = rna_tf32((xv.w - mean) * inv * gv.w + bv.w);
    outr[threadIdx.x] = o4;
}

// ---------------------------------------------------------------------------
// Row softmax over TJ_ = 2048: one block (256 thr) per row, in place.
// Output (P) RNA-rounded to tf32 for the PV GEMM.
// ---------------------------------------------------------------------------
__global__ void softmax_kernel(float* __restrict__ S) {
    const size_t row = blockIdx.x;
    float4* r4 = reinterpret_cast<float4*>(S + row * (size_t)TJ_);

    float4 v[2];
    float mx = -3.4e38f;
    #pragma unroll
    for (int i = 0; i < 2; i++) {
        v[i] = r4[threadIdx.x + i * 256];
        mx = fmaxf(mx, fmaxf(fmaxf(v[i].x, v[i].y), fmaxf(v[i].z, v[i].w)));
    }
    #pragma unroll
    for (int o = 16; o; o >>= 1) mx = fmaxf(mx, __shfl_xor_sync(0xffffffffu, mx, o));
    __shared__ float sh_m[8], sh_sum[8];
    const int w = threadIdx.x >> 5, l = threadIdx.x & 31;
    if (l == 0) sh_m[w] = mx;
    __syncthreads();
    mx = sh_m[0];
    #pragma unroll
    for (int i = 1; i < 8; i++) mx = fmaxf(mx, sh_m[i]);

    float sum = 0.f;
    #pragma unroll
    for (int i = 0; i < 2; i++) {
        v[i].x = __expf(v[i].x - mx);
        v[i].y = __expf(v[i].y - mx);
        v[i].z = __expf(v[i].z - mx);
        v[i].w = __expf(v[i].w - mx);
        sum += v[i].x + v[i].y + v[i].z + v[i].w;
    }
    #pragma unroll
    for (int o = 16; o; o >>= 1) sum += __shfl_xor_sync(0xffffffffu, sum, o);
    if (l == 0) sh_sum[w] = sum;
    __syncthreads();
    sum = 0.f;
    #pragma unroll
    for (int i = 0; i < 8; i++) sum += sh_sum[i];
    const float inv = 1.0f / sum;
    #pragma unroll
    for (int i = 0; i < 2; i++) {
        v[i].x = rna_tf32(v[i].x * inv);
        v[i].y = rna_tf32(v[i].y * inv);
        v[i].z = rna_tf32(v[i].z * inv);
        v[i].w = rna_tf32(v[i].w * inv);
        r4[threadIdx.x + i * 256] = v[i];
    }
}

// ---------------------------------------------------------------------------
// Per-batch transpose: Vt[b][n][k] = V[b][k][n]   (V: [TJ, DIM])
// (V is already RNA-rounded by the projection epilogue.)
// ---------------------------------------------------------------------------
__global__ void transpose_kernel(const float* __restrict__ in, float* __restrict__ out) {
    __shared__ float tile[32][33];
    const int b = blockIdx.z;
    in  += (size_t)b * TJ_ * DIM_;
    out += (size_t)b * TJ_ * DIM_;
    int x = blockIdx.x * 32 + threadIdx.x;   // col in V (DIM)
    int y = blockIdx.y * 32 + threadIdx.y;   // row in V (TJ)
    #pragma unroll
    for (int j = 0; j < 32; j += 8)
        tile[threadIdx.y + j][threadIdx.x] = in[(size_t)(y + j) * DIM_ + x];
    __syncthreads();
    x = blockIdx.y * 32 + threadIdx.x;       // col in Vt (TJ)
    y = blockIdx.x * 32 + threadIdx.y;       // row in Vt (DIM)
    #pragma unroll
    for (int j = 0; j < 32; j += 8)
        out[(size_t)(y + j) * TJ_ + x] = tile[threadIdx.x][threadIdx.y + j];
}

// ---------------------------------------------------------------------------
// Launch
// ---------------------------------------------------------------------------
extern "C" void kernel_launch(void* const* d_in, const int* in_sizes, int n_in,
                              void* d_out, int out_size) {
    (void)in_sizes; (void)n_in; (void)out_size;
    const float* target   = (const float*)d_in[0];
    const float* source_k = (const float*)d_in[1];
    const float* source_v = (const float*)d_in[2];
    const float* Wq = (const float*)d_in[3];
    const float* bq = (const float*)d_in[4];
    const float* Wk = (const float*)d_in[5];
    const float* bk = (const float*)d_in[6];
    const float* Wv = (const float*)d_in[7];
    const float* bv = (const float*)d_in[8];
    const float* gt = (const float*)d_in[9];
    const float* bt = (const float*)d_in[10];
    const float* gk = (const float*)d_in[11];
    const float* bk_ln = (const float*)d_in[12];
    const float* gv = (const float*)d_in[13];
    const float* bv_ln = (const float*)d_in[14];
    float* out = (float*)d_out;

    float *ln_t, *ln_k, *ln_v, *q, *k, *v, *vt, *S, *wq_r, *wk_r, *wv_r;
    cudaGetSymbolAddress((void**)&ln_t, g_ln_t);
    cudaGetSymbolAddress((void**)&ln_k, g_ln_k);
    cudaGetSymbolAddress((void**)&ln_v, g_ln_v);
    cudaGetSymbolAddress((void**)&q,    g_q);
    cudaGetSymbolAddress((void**)&k,    g_k);
    cudaGetSymbolAddress((void**)&v,    g_v);
    cudaGetSymbolAddress((void**)&vt,   g_vt);
    cudaGetSymbolAddress((void**)&S,    g_S);
    cudaGetSymbolAddress((void**)&wq_r, g_Wq);
    cudaGetSymbolAddress((void**)&wk_r, g_Wk);
    cudaGetSymbolAddress((void**)&wv_r, g_Wv);

    cudaFuncSetAttribute(gemm_tc_kernel<true, true>,
        cudaFuncAttributeMaxDynamicSharedMemorySize, SMEM_TOTAL_GEMM);
    cudaFuncSetAttribute(gemm_tc_kernel<false, false>,
        cudaFuncAttributeMaxDynamicSharedMemorySize, SMEM_TOTAL_GEMM);

    // RNA-round the weights once per launch (tiny)
    const int n4w = DIM_ * DIM_ / 4;
    round_tf32_kernel<<<n4w / 256, 256>>>(Wq, wq_r, n4w);
    round_tf32_kernel<<<n4w / 256, 256>>>(Wk, wk_r, n4w);
    round_tf32_kernel<<<n4w / 256, 256>>>(Wv, wv_r, n4w);

    // LayerNorms (outputs RNA-rounded)
    ln_kernel<<<NROWS_T, 256>>>(target,   gt, bt,    ln_t);
    ln_kernel<<<NROWS_S, 256>>>(source_k, gk, bk_ln, ln_k);
    ln_kernel<<<NROWS_S, 256>>>(source_v, gv, bv_ln, ln_v);

    // Projections: X @ W^T + b  (W: [out,in] row-major = [N,K]); outputs rounded
    dim3 gProj(DIM_ / TBN, NROWS_T / TBM, 1);
    gemm_tc_kernel<true, true><<<gProj, 256, SMEM_TOTAL_GEMM>>>(ln_t, wq_r, bq, q,
        NROWS_T, DIM_, DIM_, 1.0f, 0, 0, 0);
    gemm_tc_kernel<true, true><<<gProj, 256, SMEM_TOTAL_GEMM>>>(ln_k, wk_r, bk, k,
        NROWS_S, DIM_, DIM_, 1.0f, 0, 0, 0);
    gemm_tc_kernel<true, true><<<gProj, 256, SMEM_TOTAL_GEMM>>>(ln_v, wv_r, bv, v,
        NROWS_S, DIM_, DIM_, 1.0f, 0, 0, 0);

    // Vt[b] = V[b]^T  (so PV GEMM is in the both-K-major form)
    transpose_kernel<<<dim3(DIM_ / 32, TJ_ / 32, B_), dim3(32, 8)>>>(v, vt);

    // S = (Q K^T) * DIM^-0.5, batched over B_
    dim3 gS(TJ_ / TBN, TI_ / TBM, B_);
    gemm_tc_kernel<false, false><<<gS, 256, SMEM_TOTAL_GEMM>>>(q, k, nullptr, S,
        TI_, TJ_, DIM_, 0.03125f,
        (long long)TI_ * DIM_, (long long)TJ_ * DIM_, (long long)TI_ * TJ_);

    // softmax rows of S (output P rounded)
    softmax_kernel<<<B_ * TI_, 256>>>(S);

    // O = P @ Vt^T, batched (Vt: [DIM, TJ] K-major along TJ)
    dim3 gO(DIM_ / TBN, TI_ / TBM, B_);
    gemm_tc_kernel<false, false><<<gO, 256, SMEM_TOTAL_GEMM>>>(S, vt, nullptr, out,
        TI_, DIM_, TJ_, 1.0f,
        (long long)TI_ * TJ_, (long long)TJ_ * DIM_, (long long)TI_ * DIM_);
}

// round 5
// speedup vs baseline: 3.4755x; 1.7863x over previous
#include <cuda_runtime.h>
#include <cuda_fp16.h>
#include <cstdint>

// ---------------------------------------------------------------------------
// Problem constants
// ---------------------------------------------------------------------------
#define DIM_  1024
#define B_    8
#define TI_   2048
#define TJ_   2048
#define EPS_  1e-5f
#define NROWS_T (B_*TI_)   // 16384
#define NROWS_S (B_*TJ_)   // 16384

// ---------------------------------------------------------------------------
// Scratch (device globals — sanctioned workaround for no-alloc rule)
// ---------------------------------------------------------------------------
__device__ __half g_ln_t[(size_t)NROWS_T * DIM_];
__device__ __half g_ln_k[(size_t)NROWS_S * DIM_];
__device__ __half g_ln_v[(size_t)NROWS_S * DIM_];
__device__ __half g_q  [(size_t)NROWS_T * DIM_];
__device__ __half g_k  [(size_t)NROWS_S * DIM_];
__device__ __half g_v  [(size_t)NROWS_S * DIM_];
__device__ __half g_vt [(size_t)NROWS_S * DIM_];  // V^T per batch: [B][DIM][TJ]
__device__ float  g_S  [(size_t)B_ * TI_ * TJ_];  // logits (fp32 through softmax)
__device__ __half g_P  [(size_t)B_ * TI_ * TJ_];  // probabilities (fp16)
__device__ __half g_Wq [(size_t)DIM_ * DIM_];     // RN-converted fp16 weights
__device__ __half g_Wk [(size_t)DIM_ * DIM_];
__device__ __half g_Wv [(size_t)DIM_ * DIM_];

// ---------------------------------------------------------------------------
// PTX helpers (legacy sm_80-class only — this toolchain's ptxas target is
// sm_103 non-'a', which rejects tcgen05/TMEM)
// ---------------------------------------------------------------------------
__device__ __forceinline__ uint32_t smem_u32(const void* p) {
    uint32_t a;
    asm("{ .reg .u64 t; cvta.to.shared.u64 t, %1; cvt.u32.u64 %0, t; }"
        : "=r"(a) : "l"(p));
    return a;
}

#define CP_ASYNC16(dst_u32, src_ptr) \
    asm volatile("cp.async.cg.shared.global [%0], [%1], 16;\n" \
                 :: "r"(dst_u32), "l"(src_ptr))
#define CP_COMMIT() asm volatile("cp.async.commit_group;\n" ::: "memory")
#define CP_WAIT(n)  asm volatile("cp.async.wait_group %0;\n" :: "n"(n) : "memory")

#define LDSM4(r0, r1, r2, r3, addr) \
    asm volatile("ldmatrix.sync.aligned.m8n8.x4.shared.b16 {%0,%1,%2,%3}, [%4];" \
                 : "=r"(r0), "=r"(r1), "=r"(r2), "=r"(r3) : "r"(addr))

#define MMA_F16(d0, d1, d2, d3, a0, a1, a2, a3, b0, b1) \
    asm volatile( \
        "mma.sync.aligned.m16n8k16.row.col.f32.f16.f16.f32 " \
        "{%0,%1,%2,%3}, {%4,%5,%6,%7}, {%8,%9}, {%0,%1,%2,%3};" \
        : "+f"(d0), "+f"(d1), "+f"(d2), "+f"(d3) \
        : "r"(a0), "r"(a1), "r"(a2), "r"(a3), "r"(b0), "r"(b1))

// ---------------------------------------------------------------------------
// fp16 mma.sync GEMM with cp.async pipeline + ldmatrix fragment loads
//   C[m,n] = scale * sum_k A[m,k]*B[n,k]  (+ bias[n])
//   A: [M,K] row-major fp16, B: [N,K] row-major fp16.
//   M % 128 == 0, N % 256 == 0, K % 64 == 0.
// CTA tile 128x256, 8 warps of 64x64, BK=64 (128B rows -> same swizzle as R4),
// 4 stages. fp32 accumulate; output fp32 or fp16 (RN) per template.
// ---------------------------------------------------------------------------
constexpr int TBM = 128, TBN = 256, TBK = 64, STAGES = 4;
constexpr int A_BYTES = TBM * TBK * 2;               // 16 KB
constexpr int B_BYTES = TBN * TBK * 2;               // 32 KB
constexpr int STAGE_BYTES = A_BYTES + B_BYTES;       // 48 KB
constexpr int SMEM_TOTAL_GEMM = 1024 + STAGES * STAGE_BYTES;  // ~193 KB

template <bool HAS_BIAS, bool OUT_HALF>
__global__ __launch_bounds__(256, 1)
void gemm_f16_kernel(const __half* __restrict__ A, const __half* __restrict__ Bm,
                     const float* __restrict__ bias, void* __restrict__ Cv,
                     int M, int N, int K, float scale,
                     long long bsA, long long bsB, long long bsC) {
    extern __shared__ char smem[];
    const uint32_t tiles = (smem_u32(smem) + 1023u) & ~1023u;

    const int z = blockIdx.z;
    A  += (size_t)z * bsA;
    Bm += (size_t)z * bsB;
    const int bm = blockIdx.y * TBM;
    const int bn = blockIdx.x * TBN;

    const int tid  = threadIdx.x;
    const int lane = tid & 31;
    const int w    = tid >> 5;
    const int wm   = (w & 1) * 64;     // warp M base in tile
    const int wn   = (w >> 1) * 64;    // warp N base in tile

    // per-lane ldmatrix base offsets (within a stage; 128-byte rows)
    const int rrA = (lane & 7) + (((lane >> 3) & 1) << 3);
    const int csA = (lane >> 4) & 1;
    const int rrB = (lane & 7) + (((lane >> 4) & 1) << 3);
    const int csB = (lane >> 3) & 1;

    uint32_t Aoff[4], Boff[4];
    #pragma unroll
    for (int mf = 0; mf < 4; mf++) {
        const int row = wm + mf * 16 + rrA;
        Aoff[mf] = (uint32_t)(row * 128) + (uint32_t)((((row & 7) ^ csA) << 4));
    }
    #pragma unroll
    for (int nfp = 0; nfp < 4; nfp++) {
        const int row = wn + nfp * 16 + rrB;
        Boff[nfp] = (uint32_t)(row * 128) + (uint32_t)((((row & 7) ^ csB) << 4));
    }

    float acc[4][8][4];
    #pragma unroll
    for (int mf = 0; mf < 4; mf++)
        #pragma unroll
        for (int nf = 0; nf < 8; nf++)
            #pragma unroll
            for (int c = 0; c < 4; c++) acc[mf][nf][c] = 0.f;

    const int nst = K / TBK;

    // stage loader: swizzled 16B cp.async (A: 4/thread, B: 8/thread)
    auto load_stage = [&](int i) {
        const int s = i & (STAGES - 1);
        const uint32_t ab = tiles + s * STAGE_BYTES;
        const uint32_t bb = ab + A_BYTES;
        const int k0 = i * TBK;
        #pragma unroll
        for (int j = 0; j < 4; j++) {
            const int c   = tid + 256 * j;
            const int row = c >> 3;          // 0..127
            const int c8  = c & 7;           // 16B chunk (8 fp16)
            const uint32_t off = (uint32_t)(row * 128) +
                                 (uint32_t)(((c8 ^ (row & 7)) << 4));
            CP_ASYNC16(ab + off, A + (size_t)(bm + row) * K + k0 + c8 * 8);
        }
        #pragma unroll
        for (int j = 0; j < 8; j++) {
            const int c   = tid + 256 * j;
            const int row = c >> 3;          // 0..255
            const int c8  = c & 7;
            const uint32_t off = (uint32_t)(row * 128) +
                                 (uint32_t)(((c8 ^ (row & 7)) << 4));
            CP_ASYNC16(bb + off, Bm + (size_t)(bn + row) * K + k0 + c8 * 8);
        }
        CP_COMMIT();
    };

    load_stage(0); load_stage(1); load_stage(2);

    for (int i = 0; i < nst; i++) {
        if (i + STAGES - 2 >= nst) { CP_WAIT(0); } else { CP_WAIT(STAGES - 2); }
        __syncthreads();
        if (i + STAGES - 1 < nst) load_stage(i + STAGES - 1);

        const int s = i & (STAGES - 1);
        const uint32_t ab = tiles + s * STAGE_BYTES;
        const uint32_t bb = ab + A_BYTES;

        #pragma unroll
        for (int ks = 0; ks < 4; ks++) {     // 4 x k16 per BK=64 stage
            const uint32_t cx = (uint32_t)(ks << 5);
            uint32_t af[4][4];
            #pragma unroll
            for (int mf = 0; mf < 4; mf++)
                LDSM4(af[mf][0], af[mf][1], af[mf][2], af[mf][3],
                      (ab + Aoff[mf]) ^ cx);
            uint32_t bf[8][2];
            #pragma unroll
            for (int nfp = 0; nfp < 4; nfp++) {
                uint32_t r0, r1, r2, r3;
                LDSM4(r0, r1, r2, r3, (bb + Boff[nfp]) ^ cx);
                bf[2 * nfp][0] = r0;  bf[2 * nfp][1] = r1;
                bf[2 * nfp + 1][0] = r2;  bf[2 * nfp + 1][1] = r3;
            }
            #pragma unroll
            for (int mf = 0; mf < 4; mf++)
                #pragma unroll
                for (int nf = 0; nf < 8; nf++)
                    MMA_F16(acc[mf][nf][0], acc[mf][nf][1],
                            acc[mf][nf][2], acc[mf][nf][3],
                            af[mf][0], af[mf][1], af[mf][2], af[mf][3],
                            bf[nf][0], bf[nf][1]);
        }
    }

    // --- epilogue ---
    #pragma unroll
    for (int mf = 0; mf < 4; mf++) {
        const int r0 = bm + wm + mf * 16 + (lane >> 2);
        #pragma unroll
        for (int nf = 0; nf < 8; nf++) {
            const int c0 = bn + wn + nf * 8 + 2 * (lane & 3);
            float2 b2 = make_float2(0.f, 0.f);
            if (HAS_BIAS) b2 = *reinterpret_cast<const float2*>(bias + c0);
            const float v00 = acc[mf][nf][0] * scale + b2.x;
            const float v01 = acc[mf][nf][1] * scale + b2.y;
            const float v10 = acc[mf][nf][2] * scale + b2.x;
            const float v11 = acc[mf][nf][3] * scale + b2.y;
            if (OUT_HALF) {
                __half* C = (__half*)Cv + (size_t)z * bsC;
                *reinterpret_cast<__half2*>(C + (size_t)r0 * N + c0) =
                    __floats2half2_rn(v00, v01);
                *reinterpret_cast<__half2*>(C + (size_t)(r0 + 8) * N + c0) =
                    __floats2half2_rn(v10, v11);
            } else {
                float* C = (float*)Cv + (size_t)z * bsC;
                *reinterpret_cast<float2*>(C + (size_t)r0 * N + c0) =
                    make_float2(v00, v01);
                *reinterpret_cast<float2*>(C + (size_t)(r0 + 8) * N + c0) =
                    make_float2(v10, v11);
            }
        }
    }
}

// ---------------------------------------------------------------------------
// fp32 -> fp16 (RN) weight conversion
// ---------------------------------------------------------------------------
__global__ void cvt_h_kernel(const float* __restrict__ in,
                             __half* __restrict__ out, int n4) {
    const int i = blockIdx.x * blockDim.x + threadIdx.x;
    if (i < n4) {
        const float4 v = reinterpret_cast<const float4*>(in)[i];
        const __half2 h0 = __floats2half2_rn(v.x, v.y);
        const __half2 h1 = __floats2half2_rn(v.z, v.w);
        uint2 u;
        u.x = *reinterpret_cast<const uint32_t*>(&h0);
        u.y = *reinterpret_cast<const uint32_t*>(&h1);
        reinterpret_cast<uint2*>(out)[i] = u;
    }
}

// ---------------------------------------------------------------------------
// LayerNorm: one block (256 thr) per row of 1024; output fp16 (RN)
// ---------------------------------------------------------------------------
__global__ void ln_kernel(const float* __restrict__ x,
                          const float* __restrict__ gamma,
                          const float* __restrict__ beta,
                          __half* __restrict__ out) {
    const size_t row = blockIdx.x;
    const float4* xr = reinterpret_cast<const float4*>(x + row * DIM_);

    float4 xv = xr[threadIdx.x];
    float s  = xv.x + xv.y + xv.z + xv.w;
    float s2 = xv.x*xv.x + xv.y*xv.y + xv.z*xv.z + xv.w*xv.w;

    #pragma unroll
    for (int o = 16; o; o >>= 1) {
        s  += __shfl_xor_sync(0xffffffffu, s,  o);
        s2 += __shfl_xor_sync(0xffffffffu, s2, o);
    }
    __shared__ float sh_s[8], sh_s2[8];
    const int w = threadIdx.x >> 5, l = threadIdx.x & 31;
    if (l == 0) { sh_s[w] = s; sh_s2[w] = s2; }
    __syncthreads();
    float ts = 0.f, ts2 = 0.f;
    #pragma unroll
    for (int i = 0; i < 8; i++) { ts += sh_s[i]; ts2 += sh_s2[i]; }

    const float mean = ts * (1.0f / DIM_);
    const float var  = ts2 * (1.0f / DIM_) - mean * mean;
    const float inv  = rsqrtf(var + EPS_);

    const float4 gv = reinterpret_cast<const float4*>(gamma)[threadIdx.x];
    const float4 bv = reinterpret_cast<const float4*>(beta)[threadIdx.x];
    const __half2 h0 = __floats2half2_rn((xv.x - mean) * inv * gv.x + bv.x,
                                         (xv.y - mean) * inv * gv.y + bv.y);
    const __half2 h1 = __floats2half2_rn((xv.z - mean) * inv * gv.z + bv.z,
                                         (xv.w - mean) * inv * gv.w + bv.w);
    uint2 u;
    u.x = *reinterpret_cast<const uint32_t*>(&h0);
    u.y = *reinterpret_cast<const uint32_t*>(&h1);
    reinterpret_cast<uint2*>(out + row * DIM_)[threadIdx.x] = u;
}

// ---------------------------------------------------------------------------
// Row softmax over TJ_ = 2048: reads fp32 S, writes fp16 P
// ---------------------------------------------------------------------------
__global__ void softmax_kernel(const float* __restrict__ S, __half* __restrict__ P) {
    const size_t row = blockIdx.x;
    const float4* r4 = reinterpret_cast<const float4*>(S + row * (size_t)TJ_);
    uint2* p2 = reinterpret_cast<uint2*>(P + row * (size_t)TJ_);

    float4 v[2];
    float mx = -3.4e38f;
    #pragma unroll
    for (int i = 0; i < 2; i++) {
        v[i] = r4[threadIdx.x + i * 256];
        mx = fmaxf(mx, fmaxf(fmaxf(v[i].x, v[i].y), fmaxf(v[i].z, v[i].w)));
    }
    #pragma unroll
    for (int o = 16; o; o >>= 1) mx = fmaxf(mx, __shfl_xor_sync(0xffffffffu, mx, o));
    __shared__ float sh_m[8], sh_sum[8];
    const int w = threadIdx.x >> 5, l = threadIdx.x & 31;
    if (l == 0) sh_m[w] = mx;
    __syncthreads();
    mx = sh_m[0];
    #pragma unroll
    for (int i = 1; i < 8; i++) mx = fmaxf(mx, sh_m[i]);

    float sum = 0.f;
    #pragma unroll
    for (int i = 0; i < 2; i++) {
        v[i].x = __expf(v[i].x - mx);
        v[i].y = __expf(v[i].y - mx);
        v[i].z = __expf(v[i].z - mx);
        v[i].w = __expf(v[i].w - mx);
        sum += v[i].x + v[i].y + v[i].z + v[i].w;
    }
    #pragma unroll
    for (int o = 16; o; o >>= 1) sum += __shfl_xor_sync(0xffffffffu, sum, o);
    if (l == 0) sh_sum[w] = sum;
    __syncthreads();
    sum = 0.f;
    #pragma unroll
    for (int i = 0; i < 8; i++) sum += sh_sum[i];
    const float inv = 1.0f / sum;
    #pragma unroll
    for (int i = 0; i < 2; i++) {
        const __half2 h0 = __floats2half2_rn(v[i].x * inv, v[i].y * inv);
        const __half2 h1 = __floats2half2_rn(v[i].z * inv, v[i].w * inv);
        uint2 u;
        u.x = *reinterpret_cast<const uint32_t*>(&h0);
        u.y = *reinterpret_cast<const uint32_t*>(&h1);
        p2[threadIdx.x + i * 256] = u;
    }
}

// ---------------------------------------------------------------------------
// Per-batch fp16 transpose: Vt[b][n][k] = V[b][k][n]   (V: [TJ, DIM])
// ---------------------------------------------------------------------------
__global__ void transpose_kernel(const __half* __restrict__ in,
                                 __half* __restrict__ out) {
    __shared__ __half tile[32][33];
    const int b = blockIdx.z;
    in  += (size_t)b * TJ_ * DIM_;
    out += (size_t)b * TJ_ * DIM_;
    int x = blockIdx.x * 32 + threadIdx.x;   // col in V (DIM)
    int y = blockIdx.y * 32 + threadIdx.y;   // row in V (TJ)
    #pragma unroll
    for (int j = 0; j < 32; j += 8)
        tile[threadIdx.y + j][threadIdx.x] = in[(size_t)(y + j) * DIM_ + x];
    __syncthreads();
    x = blockIdx.y * 32 + threadIdx.x;       // col in Vt (TJ)
    y = blockIdx.x * 32 + threadIdx.y;       // row in Vt (DIM)
    #pragma unroll
    for (int j = 0; j < 32; j += 8)
        out[(size_t)(y + j) * TJ_ + x] = tile[threadIdx.x][threadIdx.y + j];
}

// ---------------------------------------------------------------------------
// Launch
// ---------------------------------------------------------------------------
extern "C" void kernel_launch(void* const* d_in, const int* in_sizes, int n_in,
                              void* d_out, int out_size) {
    (void)in_sizes; (void)n_in; (void)out_size;
    const float* target   = (const float*)d_in[0];
    const float* source_k = (const float*)d_in[1];
    const float* source_v = (const float*)d_in[2];
    const float* Wq = (const float*)d_in[3];
    const float* bq = (const float*)d_in[4];
    const float* Wk = (const float*)d_in[5];
    const float* bk = (const float*)d_in[6];
    const float* Wv = (const float*)d_in[7];
    const float* bv = (const float*)d_in[8];
    const float* gt = (const float*)d_in[9];
    const float* bt = (const float*)d_in[10];
    const float* gk = (const float*)d_in[11];
    const float* bk_ln = (const float*)d_in[12];
    const float* gv = (const float*)d_in[13];
    const float* bv_ln = (const float*)d_in[14];
    float* out = (float*)d_out;

    __half *ln_t, *ln_k, *ln_v, *q, *k, *v, *vt, *P, *wq_h, *wk_h, *wv_h;
    float *S;
    cudaGetSymbolAddress((void**)&ln_t, g_ln_t);
    cudaGetSymbolAddress((void**)&ln_k, g_ln_k);
    cudaGetSymbolAddress((void**)&ln_v, g_ln_v);
    cudaGetSymbolAddress((void**)&q,    g_q);
    cudaGetSymbolAddress((void**)&k,    g_k);
    cudaGetSymbolAddress((void**)&v,    g_v);
    cudaGetSymbolAddress((void**)&vt,   g_vt);
    cudaGetSymbolAddress((void**)&S,    g_S);
    cudaGetSymbolAddress((void**)&P,    g_P);
    cudaGetSymbolAddress((void**)&wq_h, g_Wq);
    cudaGetSymbolAddress((void**)&wk_h, g_Wk);
    cudaGetSymbolAddress((void**)&wv_h, g_Wv);

    cudaFuncSetAttribute(gemm_f16_kernel<true, true>,
        cudaFuncAttributeMaxDynamicSharedMemorySize, SMEM_TOTAL_GEMM);
    cudaFuncSetAttribute(gemm_f16_kernel<false, false>,
        cudaFuncAttributeMaxDynamicSharedMemorySize, SMEM_TOTAL_GEMM);

    // Convert weights to fp16 (RN) once per launch
    const int n4w = DIM_ * DIM_ / 4;
    cvt_h_kernel<<<n4w / 256, 256>>>(Wq, wq_h, n4w);
    cvt_h_kernel<<<n4w / 256, 256>>>(Wk, wk_h, n4w);
    cvt_h_kernel<<<n4w / 256, 256>>>(Wv, wv_h, n4w);

    // LayerNorms (fp16 out)
    ln_kernel<<<NROWS_T, 256>>>(target,   gt, bt,    ln_t);
    ln_kernel<<<NROWS_S, 256>>>(source_k, gk, bk_ln, ln_k);
    ln_kernel<<<NROWS_S, 256>>>(source_v, gv, bv_ln, ln_v);

    // Projections: X @ W^T + b  (W: [N,K] fp16); outputs fp16
    dim3 gProj(DIM_ / TBN, NROWS_T / TBM, 1);
    gemm_f16_kernel<true, true><<<gProj, 256, SMEM_TOTAL_GEMM>>>(ln_t, wq_h, bq, q,
        NROWS_T, DIM_, DIM_, 1.0f, 0, 0, 0);
    gemm_f16_kernel<true, true><<<gProj, 256, SMEM_TOTAL_GEMM>>>(ln_k, wk_h, bk, k,
        NROWS_S, DIM_, DIM_, 1.0f, 0, 0, 0);
    gemm_f16_kernel<true, true><<<gProj, 256, SMEM_TOTAL_GEMM>>>(ln_v, wv_h, bv, v,
        NROWS_S, DIM_, DIM_, 1.0f, 0, 0, 0);

    // Vt[b] = V[b]^T  (PV GEMM in both-K-major form)
    transpose_kernel<<<dim3(DIM_ / 32, TJ_ / 32, B_), dim3(32, 8)>>>(v, vt);

    // S = (Q K^T) * DIM^-0.5, batched over B_ (fp32 out)
    dim3 gS(TJ_ / TBN, TI_ / TBM, B_);
    gemm_f16_kernel<false, false><<<gS, 256, SMEM_TOTAL_GEMM>>>(q, k, nullptr, S,
        TI_, TJ_, DIM_, 0.03125f,
        (long long)TI_ * DIM_, (long long)TJ_ * DIM_, (long long)TI_ * TJ_);

    // softmax rows of S -> fp16 P
    softmax_kernel<<<B_ * TI_, 256>>>(S, P);

    // O = P @ Vt^T, batched (fp32 out to d_out)
    dim3 gO(DIM_ / TBN, TI_ / TBM, B_);
    gemm_f16_kernel<false, false><<<gO, 256, SMEM_TOTAL_GEMM>>>(P, vt, nullptr, out,
        TI_, DIM_, TJ_, 1.0f,
        (long long)TI_ * TJ_, (long long)TJ_ * DIM_, (long long)TI_ * DIM_);
}